// round 1
// baseline (speedup 1.0000x reference)
#include <cuda_runtime.h>
#include <cuda_bf16.h>
#include <cstdint>
#include <cstddef>

// ---------------------------------------------------------------------------
// Cayley-Dickson sign table:  e_i * e_j = sign(i,j) * e_{i XOR j}
// ---------------------------------------------------------------------------
constexpr int cdsign(int i, int j, int n) {
    return (n == 1) ? 1
         : (i < n/2 && j < n/2) ? cdsign(i, j, n/2)
         : (i < n/2)            ? cdsign(j - n/2, i, n/2)                      // (d a)
         : (j < n/2)            ? cdsign(i - n/2, j, n/2) * (j == 0 ? 1 : -1)  // b * conj(c)
         : -cdsign(j - n/2, i - n/2, n/2) * ((j - n/2) == 0 ? 1 : -1);         // -conj(d) b
}

struct SgnTab { signed char v[16][16]; };
constexpr SgnTab make_sgn() {
    SgnTab t{};
    for (int i = 0; i < 16; ++i)
        for (int j = 0; j < 16; ++j)
            t.v[i][j] = (signed char)cdsign(i, j, 16);
    return t;
}
__constant__ SgnTab c_SGN = make_sgn();

// ---------------------------------------------------------------------------
// Problem constants
// ---------------------------------------------------------------------------
static constexpr int B = 8, C = 128, H = 128, W = 128;
static constexpr int NPIX = B * H * W;          // 131072
static constexpr int NWIN = NPIX / 16;          // 8192
static constexpr int CH   = C * 4;              // 512

// Scratch (static device allocations; no cudaMalloc allowed)
__device__ float g_xt[NPIX * C];   // x transposed to window-major per-pixel rows
__device__ float g_xn[NPIX * C];   // LN1(x)
__device__ float g_g [NPIX * C];   // gelu(sed output)
__device__ float g_y [NPIX * C];   // after proj + residual
__device__ float g_yn[NPIX * C];   // LN2(y)
__device__ float g_h [NPIX * CH];  // MLP hidden
__device__ float g_o [NPIX * C];   // final pre-transpose

// ---------------------------------------------------------------------------
// f32x2 packed-FMA helpers (Blackwell FFMA2 — 2x fp32 throughput)
// ---------------------------------------------------------------------------
__device__ __forceinline__ unsigned long long f2u(float x, float y) {
    unsigned long long r;
    asm("mov.b64 %0, {%1, %2};" : "=l"(r) : "f"(x), "f"(y));
    return r;
}
__device__ __forceinline__ float2 u2f(unsigned long long v) {
    float2 r;
    asm("mov.b64 {%0, %1}, %2;" : "=f"(r.x), "=f"(r.y) : "l"(v));
    return r;
}
__device__ __forceinline__ void ffma2(unsigned long long& acc,
                                      unsigned long long a,
                                      unsigned long long b) {
    asm("fma.rn.f32x2 %0, %1, %2, %0;" : "+l"(acc) : "l"(a), "l"(b));
}

__device__ __forceinline__ float gelu_exact(float v) {
    return 0.5f * v * (1.0f + erff(v * 0.7071067811865476f));
}

// ---------------------------------------------------------------------------
// Kernel 1: LN1 + NCHW -> window-major transpose (writes xt and xn)
// pixel row index = ((b*32 + H/4)*32 + W/4)*16 + (H%4)*4 + (W%4)
// ---------------------------------------------------------------------------
__global__ void k_ln1(const float* __restrict__ x,
                      const float* __restrict__ g1,
                      const float* __restrict__ b1,
                      float* __restrict__ xt,
                      float* __restrict__ xn) {
    __shared__ float sh[128][33];
    __shared__ float red[2][8][32];
    __shared__ float smean[32], srstd[32];

    const int b  = blockIdx.y;
    const int s0 = blockIdx.x * 32;         // 32 consecutive spatial positions
    const int tp = threadIdx.x & 31;
    const int ty = threadIdx.x >> 5;

    const float* xb = x + (size_t)b * C * (H * W) + s0;
    float sum = 0.f, sq = 0.f;
    #pragma unroll
    for (int c0 = 0; c0 < 128; c0 += 8) {
        int c = c0 + ty;
        float v = xb[(size_t)c * (H * W) + tp];
        sh[c][tp] = v;
        sum += v; sq += v * v;
    }
    red[0][ty][tp] = sum;
    red[1][ty][tp] = sq;
    __syncthreads();
    if (ty == 0) {
        float s = 0.f, q = 0.f;
        #pragma unroll
        for (int y = 0; y < 8; ++y) { s += red[0][y][tp]; q += red[1][y][tp]; }
        float m   = s * (1.0f / 128.0f);
        float var = q * (1.0f / 128.0f) - m * m;
        smean[tp] = m;
        srstd[tp] = rsqrtf(var + 1e-5f);
    }
    __syncthreads();

    for (int l = threadIdx.x; l < 32 * 128; l += 256) {
        int p = l >> 7, c = l & 127;
        int s = s0 + p;
        int hh = s >> 7, ww = s & 127;
        int row = ((((b * 32 + (hh >> 2)) * 32 + (ww >> 2)) << 4)
                  + ((hh & 3) << 2) + (ww & 3));
        float v = sh[c][p];
        xt[(size_t)row * 128 + c] = v;
        xn[(size_t)row * 128 + c] = (v - smean[p]) * srstd[p] * g1[c] + b1[c];
    }
}

// ---------------------------------------------------------------------------
// Kernel 2: LN2 over contiguous 128-rows (warp per row)
// ---------------------------------------------------------------------------
__global__ void k_ln2(const float* __restrict__ y,
                      const float* __restrict__ g2,
                      const float* __restrict__ b2,
                      float* __restrict__ yn) {
    int row  = blockIdx.x * 8 + (threadIdx.x >> 5);
    int lane = threadIdx.x & 31;
    const float* yr = y + (size_t)row * 128;
    float v[4];
    float sum = 0.f, sq = 0.f;
    #pragma unroll
    for (int i = 0; i < 4; ++i) {
        v[i] = yr[lane + 32 * i];
        sum += v[i]; sq += v[i] * v[i];
    }
    #pragma unroll
    for (int o = 16; o; o >>= 1) {
        sum += __shfl_xor_sync(0xffffffffu, sum, o);
        sq  += __shfl_xor_sync(0xffffffffu, sq,  o);
    }
    float m  = sum * (1.0f / 128.0f);
    float rs = rsqrtf(sq * (1.0f / 128.0f) - m * m + 1e-5f);
    float* on = yn + (size_t)row * 128;
    #pragma unroll
    for (int i = 0; i < 4; ++i) {
        int c = lane + 32 * i;
        on[c] = (v[i] - m) * rs * g2[c] + b2[c];
    }
}

// ---------------------------------------------------------------------------
// Generic 128x128-tile SGEMM with FFMA2, templated epilogue.
// MODE 0: SED  (B virtual from sed_w + CD sign), epilogue gelu
// MODE 1: PROJ (+ bias + residual add)
// MODE 2: MLP1 (+ bias, gelu)
// MODE 3: MLP2 (+ bias + residual add)
// ---------------------------------------------------------------------------
template<int MODE, int Kc, int Nc>
__global__ __launch_bounds__(256)
void k_gemm(const float* __restrict__ A,
            const float* __restrict__ Bmat,
            const float* __restrict__ bias,
            const float* __restrict__ add,
            float* __restrict__ out) {
    __shared__ __align__(16) float As[16][130];                 // [k][m]
    __shared__ __align__(16) unsigned long long Bsd[16][128];   // duplicated pairs

    const int tid = threadIdx.x;
    const int tm  = tid >> 4;       // 0..15
    const int tn  = tid & 15;       // 0..15
    const int bm  = blockIdx.y;
    const int bn  = blockIdx.x;

    unsigned long long acc[4][8];
    #pragma unroll
    for (int p = 0; p < 4; ++p)
        #pragma unroll
        for (int j = 0; j < 8; ++j) acc[p][j] = 0ull;

    const float* Ab = A + (size_t)bm * 128 * Kc;

    for (int kt = 0; kt < Kc / 16; ++kt) {
        // ---- A tile: 128 rows x 16 k, stored transposed As[k][m]
        #pragma unroll
        for (int l = tid; l < 2048; l += 256) {
            int r = l >> 4, c = l & 15;
            As[c][r] = Ab[(size_t)r * Kc + kt * 16 + c];
        }
        // ---- B tile: 16 k x 128 n, value duplicated into both f32x2 lanes
        if (MODE == 0) {
            #pragma unroll
            for (int l = tid; l < 2048; l += 256) {
                int r = l >> 7, cc = l & 127;
                int kk = kt * 16 + r;
                int i  = kk >> 7;
                int j  = i ^ bn;                 // bn == k-block (Nc=2048, 128-wide)
                float s = (float)c_SGN.v[i][j];
                float v = s * Bmat[(size_t)((j << 7) + (kk & 127)) * 128 + cc];
                Bsd[r][cc] = f2u(v, v);
            }
        } else {
            #pragma unroll
            for (int l = tid; l < 2048; l += 256) {
                int r = l >> 7, cc = l & 127;
                float v = Bmat[(size_t)(kt * 16 + r) * Nc + bn * 128 + cc];
                Bsd[r][cc] = f2u(v, v);
            }
        }
        __syncthreads();

        #pragma unroll
        for (int k = 0; k < 16; ++k) {
            const unsigned long long* Arow =
                reinterpret_cast<const unsigned long long*>(&As[k][0]);
            unsigned long long ap[4];
            ap[0] = Arow[tm * 2];
            ap[1] = Arow[tm * 2 + 1];
            ap[2] = Arow[32 + tm * 2];
            ap[3] = Arow[32 + tm * 2 + 1];
            unsigned long long bp[8];
            #pragma unroll
            for (int j = 0; j < 4; ++j) {
                bp[j]     = Bsd[k][tn * 4 + j];
                bp[4 + j] = Bsd[k][64 + tn * 4 + j];
            }
            #pragma unroll
            for (int p = 0; p < 4; ++p)
                #pragma unroll
                for (int j = 0; j < 8; ++j)
                    ffma2(acc[p][j], ap[p], bp[j]);
        }
        __syncthreads();
    }

    // ---- epilogue
    #pragma unroll
    for (int p = 0; p < 4; ++p) {
        int rbase = (p < 2) ? (tm * 4 + 2 * p) : (64 + tm * 4 + 2 * (p - 2));
        size_t grow0 = ((size_t)bm * 128 + rbase)     * Nc + (size_t)bn * 128;
        size_t grow1 = ((size_t)bm * 128 + rbase + 1) * Nc + (size_t)bn * 128;
        #pragma unroll
        for (int j = 0; j < 8; ++j) {
            int c = (j < 4) ? (tn * 4 + j) : (64 + tn * 4 + j - 4);
            float2 v2 = u2f(acc[p][j]);
            float v0 = v2.x, v1 = v2.y;
            if (MODE == 0) {
                v0 = gelu_exact(v0);
                v1 = gelu_exact(v1);
            } else if (MODE == 2) {
                float bb = bias[bn * 128 + c];
                v0 = gelu_exact(v0 + bb);
                v1 = gelu_exact(v1 + bb);
            } else {  // MODE 1 or 3
                float bb = bias[bn * 128 + c];
                v0 = v0 + bb + add[grow0 + c];
                v1 = v1 + bb + add[grow1 + c];
            }
            out[grow0 + c] = v0;
            out[grow1 + c] = v1;
        }
    }
}

// ---------------------------------------------------------------------------
// Kernel: window-major -> NCHW output transpose
// ---------------------------------------------------------------------------
__global__ void k_out(const float* __restrict__ o, float* __restrict__ out) {
    __shared__ float sh[16][513];
    const int c0 = blockIdx.x * 16;
    const int hb = blockIdx.y;     // window row (4 H-rows)
    const int b  = blockIdx.z;

    for (int l = threadIdx.x; l < 512 * 16; l += 256) {
        int px = l >> 4, c = l & 15;
        int hh = px >> 7, ww = px & 127;
        int row = (((b * 32 + hb) * 32 + (ww >> 2)) << 4) + (hh << 2) + (ww & 3);
        sh[c][px] = o[(size_t)row * 128 + c0 + c];
    }
    __syncthreads();
    for (int l = threadIdx.x; l < 512 * 16; l += 256) {
        int c = l >> 9, rem = l & 511;
        int hh = rem >> 7, ww = rem & 127;
        out[(((size_t)b * 128 + c0 + c) * 128 + (hb * 4 + hh)) * 128 + ww] =
            sh[c][hh * 128 + ww];
    }
}

// ---------------------------------------------------------------------------
// Launch
// ---------------------------------------------------------------------------
extern "C" void kernel_launch(void* const* d_in, const int* in_sizes, int n_in,
                              void* d_out, int out_size) {
    const float* x      = (const float*)d_in[0];
    const float* gamma1 = (const float*)d_in[1];
    const float* beta1  = (const float*)d_in[2];
    const float* sed_w  = (const float*)d_in[3];
    const float* w_proj = (const float*)d_in[4];
    const float* b_proj = (const float*)d_in[5];
    const float* gamma2 = (const float*)d_in[6];
    const float* beta2  = (const float*)d_in[7];
    const float* w1     = (const float*)d_in[8];
    const float* b1     = (const float*)d_in[9];
    const float* w2     = (const float*)d_in[10];
    const float* b2     = (const float*)d_in[11];
    float* out = (float*)d_out;

    float *xt, *xn, *g, *y, *yn, *h, *o;
    cudaGetSymbolAddress((void**)&xt, g_xt);
    cudaGetSymbolAddress((void**)&xn, g_xn);
    cudaGetSymbolAddress((void**)&g,  g_g);
    cudaGetSymbolAddress((void**)&y,  g_y);
    cudaGetSymbolAddress((void**)&yn, g_yn);
    cudaGetSymbolAddress((void**)&h,  g_h);
    cudaGetSymbolAddress((void**)&o,  g_o);

    // 1) LN1 + transpose to window-major
    k_ln1<<<dim3(512, 8), 256>>>(x, gamma1, beta1, xt, xn);

    // 2) SED: [8192 x 2048] @ virtual[2048 x 2048], gelu epilogue
    k_gemm<0, 2048, 2048><<<dim3(16, 64), 256>>>(xn, sed_w, nullptr, nullptr, g);

    // 3) proj: [131072 x 128] @ [128 x 128] + b_proj + xt
    k_gemm<1, 128, 128><<<dim3(1, 1024), 256>>>(g, w_proj, b_proj, xt, y);

    // 4) LN2
    k_ln2<<<NPIX / 8, 256>>>(y, gamma2, beta2, yn);

    // 5) MLP1: [131072 x 128] @ [128 x 512] + b1, gelu
    k_gemm<2, 128, 512><<<dim3(4, 1024), 256>>>(yn, w1, b1, nullptr, h);

    // 6) MLP2: [131072 x 512] @ [512 x 128] + b2 + y
    k_gemm<3, 512, 128><<<dim3(1, 1024), 256>>>(h, w2, b2, y, o);

    // 7) transpose to NCHW
    k_out<<<dim3(8, 32, 8), 256>>>(o, out);
}

// round 3
// speedup vs baseline: 4.4378x; 4.4378x over previous
#include <cuda_runtime.h>
#include <cuda_bf16.h>
#include <cstdint>
#include <cstddef>

// ---------------------------------------------------------------------------
// Cayley-Dickson sign table:  e_i * e_j = sign(i,j) * e_{i XOR j}
// ---------------------------------------------------------------------------
constexpr int cdsign(int i, int j, int n) {
    return (n == 1) ? 1
         : (i < n/2 && j < n/2) ? cdsign(i, j, n/2)
         : (i < n/2)            ? cdsign(j - n/2, i, n/2)
         : (j < n/2)            ? cdsign(i - n/2, j, n/2) * (j == 0 ? 1 : -1)
         : -cdsign(j - n/2, i - n/2, n/2) * ((j - n/2) == 0 ? 1 : -1);
}
struct SgnTab { signed char v[16][16]; };
constexpr SgnTab make_sgn() {
    SgnTab t{};
    for (int i = 0; i < 16; ++i)
        for (int j = 0; j < 16; ++j)
            t.v[i][j] = (signed char)cdsign(i, j, 16);
    return t;
}
__constant__ SgnTab c_SGN = make_sgn();

// ---------------------------------------------------------------------------
static constexpr int C = 128, NPIX = 8 * 128 * 128;   // 131072
static constexpr int CH = 512;

// fp32 buffers
__device__ float g_xt[NPIX * C];
__device__ float g_y [NPIX * C];
__device__ float g_o [NPIX * C];

// bf16 split operand buffers (256B aligned for cp.async.16)
__device__ __align__(256) __nv_bfloat16 g_xnh[NPIX * C];
__device__ __align__(256) __nv_bfloat16 g_xnl[NPIX * C];
__device__ __align__(256) __nv_bfloat16 g_gh [NPIX * C];
__device__ __align__(256) __nv_bfloat16 g_gl [NPIX * C];
__device__ __align__(256) __nv_bfloat16 g_ynh[NPIX * C];
__device__ __align__(256) __nv_bfloat16 g_ynl[NPIX * C];
__device__ __align__(256) __nv_bfloat16 g_hh [NPIX * CH];
__device__ __align__(256) __nv_bfloat16 g_hl [NPIX * CH];
// weight (B^T, n-major rows of K) buffers
__device__ __align__(256) __nv_bfloat16 g_bth[2048 * 2048];
__device__ __align__(256) __nv_bfloat16 g_btl[2048 * 2048];
__device__ __align__(256) __nv_bfloat16 g_bph[128 * 128];
__device__ __align__(256) __nv_bfloat16 g_bpl[128 * 128];
__device__ __align__(256) __nv_bfloat16 g_b1h[512 * 128];
__device__ __align__(256) __nv_bfloat16 g_b1l[512 * 128];
__device__ __align__(256) __nv_bfloat16 g_b2h[128 * 512];
__device__ __align__(256) __nv_bfloat16 g_b2l[128 * 512];

// ---------------------------------------------------------------------------
// PTX helpers (sm_80-compatible only: cp.async, ldmatrix, mma.sync)
// ---------------------------------------------------------------------------
__device__ __forceinline__ uint32_t smem_u32(const void* p) {
    uint32_t a;
    asm("{ .reg .u64 t; cvta.to.shared.u64 t, %1; cvt.u32.u64 %0, t; }"
        : "=r"(a) : "l"(p));
    return a;
}
__device__ __forceinline__ void cp16(uint32_t dst, const void* src) {
    asm volatile("cp.async.cg.shared.global [%0], [%1], 16;" :: "r"(dst), "l"(src));
}
#define CP_COMMIT() asm volatile("cp.async.commit_group;" ::: "memory")
template<int N>
__device__ __forceinline__ void cp_wait() {
    asm volatile("cp.async.wait_group %0;" :: "n"(N) : "memory");
}
__device__ __forceinline__ void ldsm_x4(uint32_t addr, uint32_t* r) {
    asm volatile("ldmatrix.sync.aligned.m8n8.x4.shared.b16 {%0,%1,%2,%3}, [%4];"
        : "=r"(r[0]), "=r"(r[1]), "=r"(r[2]), "=r"(r[3]) : "r"(addr));
}
__device__ __forceinline__ void mma16816(float* c, const uint32_t* a, const uint32_t* b) {
    asm volatile("mma.sync.aligned.m16n8k16.row.col.f32.bf16.bf16.f32 "
        "{%0,%1,%2,%3}, {%4,%5,%6,%7}, {%8,%9}, {%0,%1,%2,%3};"
        : "+f"(c[0]), "+f"(c[1]), "+f"(c[2]), "+f"(c[3])
        : "r"(a[0]), "r"(a[1]), "r"(a[2]), "r"(a[3]), "r"(b[0]), "r"(b[1]));
}
__device__ __forceinline__ uint32_t swz(uint32_t off) {
    return off ^ ((off >> 3) & 0x70);
}
__device__ __forceinline__ float gelu_exact(float v) {
    return 0.5f * v * (1.0f + erff(v * 0.7071067811865476f));
}
__device__ __forceinline__ void split_bf16(float v, __nv_bfloat16& h, __nv_bfloat16& l) {
    h = __float2bfloat16_rn(v);
    l = __float2bfloat16_rn(v - __bfloat162float(h));
}

// ---------------------------------------------------------------------------
// LN1 + NCHW -> window-major (writes xt fp32 and xn hi/lo bf16)
// ---------------------------------------------------------------------------
__global__ void k_ln1(const float* __restrict__ x,
                      const float* __restrict__ g1,
                      const float* __restrict__ b1,
                      float* __restrict__ xt,
                      __nv_bfloat16* __restrict__ xnh,
                      __nv_bfloat16* __restrict__ xnl) {
    __shared__ float sh[128][33];
    __shared__ float red[2][8][32];
    __shared__ float smean[32], srstd[32];

    const int b  = blockIdx.y;
    const int s0 = blockIdx.x * 32;
    const int tp = threadIdx.x & 31;
    const int ty = threadIdx.x >> 5;

    const float* xb = x + (size_t)b * 128 * 16384 + s0;
    float sum = 0.f, sq = 0.f;
    #pragma unroll
    for (int c0 = 0; c0 < 128; c0 += 8) {
        int c = c0 + ty;
        float v = xb[(size_t)c * 16384 + tp];
        sh[c][tp] = v;
        sum += v; sq += v * v;
    }
    red[0][ty][tp] = sum; red[1][ty][tp] = sq;
    __syncthreads();
    if (ty == 0) {
        float s = 0.f, q = 0.f;
        #pragma unroll
        for (int y = 0; y < 8; ++y) { s += red[0][y][tp]; q += red[1][y][tp]; }
        float m = s * (1.0f / 128.0f);
        smean[tp] = m;
        srstd[tp] = rsqrtf(q * (1.0f / 128.0f) - m * m + 1e-5f);
    }
    __syncthreads();

    for (int l = threadIdx.x; l < 32 * 128; l += 256) {
        int p = l >> 7, c = l & 127;
        int s = s0 + p;
        int hh = s >> 7, ww = s & 127;
        int row = ((((b * 32 + (hh >> 2)) * 32 + (ww >> 2)) << 4)
                  + ((hh & 3) << 2) + (ww & 3));
        float v = sh[c][p];
        size_t idx = (size_t)row * 128 + c;
        xt[idx] = v;
        float nv = (v - smean[p]) * srstd[p] * g1[c] + b1[c];
        __nv_bfloat16 h, lo; split_bf16(nv, h, lo);
        xnh[idx] = h; xnl[idx] = lo;
    }
}

// ---------------------------------------------------------------------------
// LN2 (warp per 128-row), writes yn hi/lo bf16
// ---------------------------------------------------------------------------
__global__ void k_ln2(const float* __restrict__ y,
                      const float* __restrict__ g2,
                      const float* __restrict__ b2,
                      __nv_bfloat16* __restrict__ ynh,
                      __nv_bfloat16* __restrict__ ynl) {
    int row  = blockIdx.x * 8 + (threadIdx.x >> 5);
    int lane = threadIdx.x & 31;
    const float* yr = y + (size_t)row * 128;
    float v[4]; float sum = 0.f, sq = 0.f;
    #pragma unroll
    for (int i = 0; i < 4; ++i) {
        v[i] = yr[lane + 32 * i]; sum += v[i]; sq += v[i] * v[i];
    }
    #pragma unroll
    for (int o = 16; o; o >>= 1) {
        sum += __shfl_xor_sync(0xffffffffu, sum, o);
        sq  += __shfl_xor_sync(0xffffffffu, sq,  o);
    }
    float m  = sum * (1.0f / 128.0f);
    float rs = rsqrtf(sq * (1.0f / 128.0f) - m * m + 1e-5f);
    #pragma unroll
    for (int i = 0; i < 4; ++i) {
        int c = lane + 32 * i;
        float nv = (v[i] - m) * rs * g2[c] + b2[c];
        __nv_bfloat16 h, lo; split_bf16(nv, h, lo);
        size_t idx = (size_t)row * 128 + c;
        ynh[idx] = h; ynl[idx] = lo;
    }
}

// ---------------------------------------------------------------------------
// Weight preps
// ---------------------------------------------------------------------------
__global__ void k_prep_sed(const float* __restrict__ sed_w,
                           __nv_bfloat16* __restrict__ bh,
                           __nv_bfloat16* __restrict__ bl) {
    int n = blockIdx.x;
    int nblk = n >> 7, d = n & 127;
    for (int k = threadIdx.x; k < 2048; k += 128) {
        int i = k >> 7, c = k & 127;
        int j = i ^ nblk;
        float s = (float)c_SGN.v[i][j];
        float v = s * __ldg(&sed_w[(size_t)(j * 128 + c) * 128 + d]);
        __nv_bfloat16 h, lo; split_bf16(v, h, lo);
        size_t idx = (size_t)n * 2048 + k;
        bh[idx] = h; bl[idx] = lo;
    }
}

__global__ void k_prep_w(const float* __restrict__ W, int K, int N,
                         __nv_bfloat16* __restrict__ bh,
                         __nv_bfloat16* __restrict__ bl) {
    int n = blockIdx.x;
    for (int k = threadIdx.x; k < K; k += 128) {
        float v = __ldg(&W[(size_t)k * N + n]);
        __nv_bfloat16 h, lo; split_bf16(v, h, lo);
        size_t idx = (size_t)n * K + k;
        bh[idx] = h; bl[idx] = lo;
    }
}

// ---------------------------------------------------------------------------
// HMMA GEMM: 128x128 CTA tile, 8 warps (4m x 2n), warp tile 32x64.
// bf16 split precision: D = Ah*Bh + Ah*Bl + Al*Bh (fp32 accum).
// Double-buffered cp.async, SW128 swizzle, fused epilogue.
// MODE 0: gelu -> bf16 hi/lo        (SED)
// MODE 1: +bias +add -> fp32        (proj)
// MODE 2: gelu(+bias) -> bf16 hi/lo (MLP1)
// MODE 3: +bias +add -> fp32        (MLP2)
// ---------------------------------------------------------------------------
static constexpr int TILE_B = 16384;                 // 128 rows x 128 bytes
static constexpr int SMEM_TOTAL = 8 * TILE_B;        // 2 stages x 4 tiles

template<int MODE, int KITERS, int NTOT>
__global__ void __launch_bounds__(256, 1)
k_tc(const __nv_bfloat16* __restrict__ Ah, const __nv_bfloat16* __restrict__ Al,
     const __nv_bfloat16* __restrict__ Bh, const __nv_bfloat16* __restrict__ Bl,
     const float* __restrict__ bias, const float* __restrict__ add,
     float* __restrict__ outf,
     __nv_bfloat16* __restrict__ outh, __nv_bfloat16* __restrict__ outl) {
    extern __shared__ __align__(1024) char smem[];
    const uint32_t sb  = smem_u32(smem);
    const int tid  = threadIdx.x;
    const int wid  = tid >> 5;
    const int lane = tid & 31;
    const int wm   = wid & 3;        // M 32-row block
    const int wn   = wid >> 2;       // N 64-col block
    const int m0 = blockIdx.y * 128;
    const int n0 = blockIdx.x * 128;
    const size_t pitch = (size_t)KITERS * 128;   // bytes per row

    const char* src[4] = {
        (const char*)Ah + (size_t)m0 * pitch,
        (const char*)Al + (size_t)m0 * pitch,
        (const char*)Bh + (size_t)n0 * pitch,
        (const char*)Bl + (size_t)n0 * pitch
    };

    float acc[2][8][4];
    #pragma unroll
    for (int mt = 0; mt < 2; ++mt)
        #pragma unroll
        for (int nt = 0; nt < 8; ++nt)
            #pragma unroll
            for (int q = 0; q < 4; ++q) acc[mt][nt][q] = 0.f;

    // stage loader: 4 tiles, 1024 cp16 per tile, 256 threads
    auto load_stage = [&](int stage, int kt) {
        #pragma unroll
        for (int t = 0; t < 4; ++t) {
            uint32_t tb = sb + (uint32_t)(stage * 4 + t) * TILE_B;
            const char* base = src[t] + (size_t)kt * 128;
            #pragma unroll
            for (int i = 0; i < 4; ++i) {
                int l  = tid + (i << 8);
                int r  = l >> 3, ch = l & 7;
                uint32_t off = (uint32_t)(r * 128 + ch * 16);
                cp16(tb + swz(off), base + (size_t)r * pitch + ch * 16);
            }
        }
    };

    // ldmatrix lane address components
    const int a_row = wm * 32 + (lane & 15);                      // + mt*16
    const int a_kc  = (lane >> 4);                                // + 2*ks
    const int b_row = wn * 64 + (lane & 7) + ((lane >> 4) & 1) * 8;  // + nt*16
    const int b_kc  = ((lane >> 3) & 1);                          // + 2*ks

    load_stage(0, 0);
    CP_COMMIT();

    for (int it = 0; it < KITERS; ++it) {
        const int buf = it & 1;
        if (it + 1 < KITERS) {
            load_stage(1 - buf, it + 1);
            CP_COMMIT();
            cp_wait<1>();
        } else {
            cp_wait<0>();
        }
        __syncthreads();

        const uint32_t bAh = sb + (uint32_t)(buf * 4 + 0) * TILE_B;
        const uint32_t bAl = sb + (uint32_t)(buf * 4 + 1) * TILE_B;
        const uint32_t bBh = sb + (uint32_t)(buf * 4 + 2) * TILE_B;
        const uint32_t bBl = sb + (uint32_t)(buf * 4 + 3) * TILE_B;

        #pragma unroll
        for (int ks = 0; ks < 4; ++ks) {
            uint32_t ah[2][4], al[2][4], bh[4][4], bl[4][4];
            #pragma unroll
            for (int mt = 0; mt < 2; ++mt) {
                uint32_t off = swz((uint32_t)((a_row + mt * 16) * 128
                                              + (a_kc + 2 * ks) * 16));
                ldsm_x4(bAh + off, ah[mt]);
                ldsm_x4(bAl + off, al[mt]);
            }
            #pragma unroll
            for (int nt = 0; nt < 4; ++nt) {
                uint32_t off = swz((uint32_t)((b_row + nt * 16) * 128
                                              + (b_kc + 2 * ks) * 16));
                ldsm_x4(bBh + off, bh[nt]);
                ldsm_x4(bBl + off, bl[nt]);
            }
            #pragma unroll
            for (int mt = 0; mt < 2; ++mt)
                #pragma unroll
                for (int nt = 0; nt < 8; ++nt) {
                    const uint32_t* bfh = &bh[nt >> 1][(nt & 1) * 2];
                    const uint32_t* bfl = &bl[nt >> 1][(nt & 1) * 2];
                    mma16816(acc[mt][nt], ah[mt], bfh);
                    mma16816(acc[mt][nt], ah[mt], bfl);
                    mma16816(acc[mt][nt], al[mt], bfh);
                }
        }
        __syncthreads();
    }

    // ---- epilogue
    #pragma unroll
    for (int mt = 0; mt < 2; ++mt) {
        const int row0 = m0 + wm * 32 + mt * 16 + (lane >> 2);
        #pragma unroll
        for (int nt = 0; nt < 8; ++nt) {
            const int col = n0 + wn * 64 + nt * 8 + (lane & 3) * 2;
            float v[4] = { acc[mt][nt][0], acc[mt][nt][1],
                           acc[mt][nt][2], acc[mt][nt][3] };
            if (MODE == 2 || MODE == 1 || MODE == 3) {
                float bb0 = __ldg(&bias[col]), bb1 = __ldg(&bias[col + 1]);
                v[0] += bb0; v[1] += bb1; v[2] += bb0; v[3] += bb1;
            }
            const size_t o0 = (size_t)row0 * NTOT + col;
            const size_t o1 = (size_t)(row0 + 8) * NTOT + col;
            if (MODE == 0 || MODE == 2) {
                #pragma unroll
                for (int q = 0; q < 4; ++q) v[q] = gelu_exact(v[q]);
                __nv_bfloat16 h0, l0, h1, l1;
                split_bf16(v[0], h0, l0); split_bf16(v[1], h1, l1);
                *(__nv_bfloat162*)(outh + o0) = __halves2bfloat162(h0, h1);
                *(__nv_bfloat162*)(outl + o0) = __halves2bfloat162(l0, l1);
                split_bf16(v[2], h0, l0); split_bf16(v[3], h1, l1);
                *(__nv_bfloat162*)(outh + o1) = __halves2bfloat162(h0, h1);
                *(__nv_bfloat162*)(outl + o1) = __halves2bfloat162(l0, l1);
            } else {
                float2 a0 = *(const float2*)(add + o0);
                float2 a1 = *(const float2*)(add + o1);
                *(float2*)(outf + o0) = make_float2(v[0] + a0.x, v[1] + a0.y);
                *(float2*)(outf + o1) = make_float2(v[2] + a1.x, v[3] + a1.y);
            }
        }
    }
}

// ---------------------------------------------------------------------------
// window-major -> NCHW output transpose
// ---------------------------------------------------------------------------
__global__ void k_out(const float* __restrict__ o, float* __restrict__ out) {
    __shared__ float sh[16][513];
    const int c0 = blockIdx.x * 16;
    const int hb = blockIdx.y;
    const int b  = blockIdx.z;

    for (int l = threadIdx.x; l < 512 * 16; l += 256) {
        int px = l >> 4, c = l & 15;
        int hh = px >> 7, ww = px & 127;
        int row = (((b * 32 + hb) * 32 + (ww >> 2)) << 4) + (hh << 2) + (ww & 3);
        sh[c][px] = o[(size_t)row * 128 + c0 + c];
    }
    __syncthreads();
    for (int l = threadIdx.x; l < 512 * 16; l += 256) {
        int c = l >> 9, rem = l & 511;
        int hh = rem >> 7, ww = rem & 127;
        out[(((size_t)b * 128 + c0 + c) * 128 + (hb * 4 + hh)) * 128 + ww] =
            sh[c][hh * 128 + ww];
    }
}

// ---------------------------------------------------------------------------
// Launch
// ---------------------------------------------------------------------------
extern "C" void kernel_launch(void* const* d_in, const int* in_sizes, int n_in,
                              void* d_out, int out_size) {
    const float* x      = (const float*)d_in[0];
    const float* gamma1 = (const float*)d_in[1];
    const float* beta1  = (const float*)d_in[2];
    const float* sed_w  = (const float*)d_in[3];
    const float* w_proj = (const float*)d_in[4];
    const float* b_proj = (const float*)d_in[5];
    const float* gamma2 = (const float*)d_in[6];
    const float* beta2  = (const float*)d_in[7];
    const float* w1     = (const float*)d_in[8];
    const float* b1     = (const float*)d_in[9];
    const float* w2     = (const float*)d_in[10];
    const float* b2     = (const float*)d_in[11];
    float* out = (float*)d_out;

    float *xt, *y, *o;
    __nv_bfloat16 *xnh, *xnl, *gh, *gl, *ynh, *ynl, *hh, *hl;
    __nv_bfloat16 *bth, *btl, *bph, *bpl, *b1h, *b1l, *b2h, *b2l;
    cudaGetSymbolAddress((void**)&xt,  g_xt);
    cudaGetSymbolAddress((void**)&y,   g_y);
    cudaGetSymbolAddress((void**)&o,   g_o);
    cudaGetSymbolAddress((void**)&xnh, g_xnh);
    cudaGetSymbolAddress((void**)&xnl, g_xnl);
    cudaGetSymbolAddress((void**)&gh,  g_gh);
    cudaGetSymbolAddress((void**)&gl,  g_gl);
    cudaGetSymbolAddress((void**)&ynh, g_ynh);
    cudaGetSymbolAddress((void**)&ynl, g_ynl);
    cudaGetSymbolAddress((void**)&hh,  g_hh);
    cudaGetSymbolAddress((void**)&hl,  g_hl);
    cudaGetSymbolAddress((void**)&bth, g_bth);
    cudaGetSymbolAddress((void**)&btl, g_btl);
    cudaGetSymbolAddress((void**)&bph, g_bph);
    cudaGetSymbolAddress((void**)&bpl, g_bpl);
    cudaGetSymbolAddress((void**)&b1h, g_b1h);
    cudaGetSymbolAddress((void**)&b1l, g_b1l);
    cudaGetSymbolAddress((void**)&b2h, g_b2h);
    cudaGetSymbolAddress((void**)&b2l, g_b2l);

    cudaFuncSetAttribute(k_tc<0, 32, 2048>, cudaFuncAttributeMaxDynamicSharedMemorySize, SMEM_TOTAL);
    cudaFuncSetAttribute(k_tc<1, 2, 128>,   cudaFuncAttributeMaxDynamicSharedMemorySize, SMEM_TOTAL);
    cudaFuncSetAttribute(k_tc<2, 2, 512>,   cudaFuncAttributeMaxDynamicSharedMemorySize, SMEM_TOTAL);
    cudaFuncSetAttribute(k_tc<3, 8, 128>,   cudaFuncAttributeMaxDynamicSharedMemorySize, SMEM_TOTAL);

    // weight preps
    k_prep_sed<<<2048, 128>>>(sed_w, bth, btl);
    k_prep_w<<<128, 128>>>(w_proj, 128, 128, bph, bpl);
    k_prep_w<<<512, 128>>>(w1, 128, 512, b1h, b1l);
    k_prep_w<<<128, 128>>>(w2, 512, 128, b2h, b2l);

    // 1) LN1 + transpose
    k_ln1<<<dim3(512, 8), 256>>>(x, gamma1, beta1, xt, xnh, xnl);

    // 2) SED: [8192 x 2048] @ Wbig^T, gelu
    k_tc<0, 32, 2048><<<dim3(16, 64), 256, SMEM_TOTAL>>>(
        xnh, xnl, bth, btl, nullptr, nullptr, nullptr, gh, gl);

    // 3) proj: [131072 x 128] @ w_proj + b_proj + xt
    k_tc<1, 2, 128><<<dim3(1, 1024), 256, SMEM_TOTAL>>>(
        gh, gl, bph, bpl, b_proj, xt, y, nullptr, nullptr);

    // 4) LN2
    k_ln2<<<NPIX / 8, 256>>>(y, gamma2, beta2, ynh, ynl);

    // 5) MLP1: @ w1 + b1, gelu
    k_tc<2, 2, 512><<<dim3(4, 1024), 256, SMEM_TOTAL>>>(
        ynh, ynl, b1h, b1l, b1, nullptr, nullptr, hh, hl);

    // 6) MLP2: @ w2 + b2 + y
    k_tc<3, 8, 128><<<dim3(1, 1024), 256, SMEM_TOTAL>>>(
        hh, hl, b2h, b2l, b2, y, o, nullptr, nullptr);

    // 7) NCHW transpose
    k_out<<<dim3(8, 32, 8), 256>>>(o, out);
}